// round 13
// baseline (speedup 1.0000x reference)
#include <cuda_runtime.h>
#include <cuda_fp16.h>
#include <cstdint>
#include <math.h>

#define NB    2
#define NPTS  16384
#define MPTS  4096
#define CIN   64
#define COUT  128
#define EPSF  1e-10f

#define NSPLIT   16
#define NPART    (NPTS/NSPLIT)      // 1024
#define NCHUNKS  (NPART/128)        // 8
#define NTILES   (NPTS/128)         // 128 per batch
#define MTILES   (MPTS/128)         // 32
#define NUNITS   (MTILES*NSPLIT*NB) // 1024
#define NCTA     152

#define XYZ_OFF  0
#define FEAT_OFF (NB*MPTS*3)
#define IDX_OFF  (FEAT_OFF + NB*COUT*MPTS)

// tile block: [128 rows][64 fp16 cols] SW128 image = 16384 B
// per ntile: [f_a kh0, f_a kh1, f_b kh0, f_b kh1] = 65536 B contiguous
#define TILE_BYTES   16384
#define SPLIT_BYTES  32768
#define CHUNK_BYTES  65536

// ---------------- device scratch ----------------
__device__ __align__(1024) unsigned char g_fsplit[(size_t)NB*NTILES*2*SPLIT_BYTES];  // 16.8 MB
__device__ __align__(1024) unsigned char g_w2split[(size_t)MTILES*2*SPLIT_BYTES];    // 2 MB
__device__ unsigned long long  g_best[NB*MPTS];
__device__ int                 g_idx[NB*MPTS];
__device__ int                 g_ctr;

// ---------------- helpers ----------------
__device__ __forceinline__ uint32_t smem_u32(const void* p) {
    uint32_t a;
    asm("{ .reg .u64 t; cvta.to.shared.u64 t, %1; cvt.u32.u64 %0, t; }" : "=r"(a) : "l"(p));
    return a;
}
#define SW128(x) ((x) ^ (((x) >> 3) & 0x70))

__device__ __forceinline__ uint32_t enc_f(float x) {
    uint32_t u = __float_as_uint(x);
    return u ^ (((uint32_t)((int32_t)u >> 31)) | 0x80000000u);
}
__device__ __forceinline__ uint32_t pk2h(__half lo, __half hi) {
    __half2 t(lo, hi);
    return *(uint32_t*)&t;
}
// fast accurate -ln(x) for normal fp32 x: atanh-form poly, abs err ~1e-7,
// near-exact relative accuracy for x near 1 (where the argmax winners live).
__device__ __forceinline__ float fast_nlog(float x) {
    int i = __float_as_int(x);
    int tt = i - 0x3F3504F3;                   // bits of sqrt(0.5)
    int e  = tt >> 23;
    float m = __int_as_float(i - (e << 23));   // m in [0.7071, 1.4142)
    float s = __fdividef(m - 1.0f, m + 1.0f);  // |s| <= 0.1716
    float s2 = s * s;
    float p = fmaf(s2, 0.11111111f, 0.14285715f);
    p = fmaf(s2, p, 0.2f);
    p = fmaf(s2, p, 0.33333334f);
    p = fmaf(s2, p, 1.0f);
    float lm = (s + s) * p;                    // ln(m)
    float ef = (float)e;
    float res = fmaf(ef, -0.693359375f, -lm);  // -e*ln2_hi - ln(m)
    return fmaf(ef, 2.12194440e-4f, res);      // + e*ln2_lo_neg
}

__device__ __forceinline__ void ldsm_x4(uint32_t* r, uint32_t addr) {
    asm volatile("ldmatrix.sync.aligned.m8n8.x4.shared.b16 {%0,%1,%2,%3}, [%4];"
        : "=r"(r[0]), "=r"(r[1]), "=r"(r[2]), "=r"(r[3]) : "r"(addr));
}
__device__ __forceinline__ void mma16816(float* c, const uint32_t* a, const uint32_t* b) {
    asm volatile("mma.sync.aligned.m16n8k16.row.col.f32.f16.f16.f32 "
        "{%0,%1,%2,%3}, {%4,%5,%6,%7}, {%8,%9}, {%0,%1,%2,%3};"
        : "+f"(c[0]), "+f"(c[1]), "+f"(c[2]), "+f"(c[3])
        : "r"(a[0]), "r"(a[1]), "r"(a[2]), "r"(a[3]), "r"(b[0]), "r"(b[1]));
}
__device__ __forceinline__ void cp16(uint32_t dst, const void* src) {
    asm volatile("cp.async.cg.shared.global [%0], [%1], 16;" :: "r"(dst), "l"(src) : "memory");
}
#define CP_COMMIT() asm volatile("cp.async.commit_group;" ::: "memory")
#define CP_WAIT0()  asm volatile("cp.async.wait_group 0;" ::: "memory")

// ---------------- kernel W: split 64*W2^T into fp16 SW128 tiles + init ----------------
__global__ void k_w2split(const float* __restrict__ W2) {
    int mt = blockIdx.x, ml = threadIdx.x;
    if (mt == 0 && ml == 0) g_ctr = 0;
    for (int i = mt * 128 + ml; i < NB * MPTS; i += MTILES * 128) g_best[i] = 0ULL;
    unsigned char* base = g_w2split + (size_t)mt * 2 * SPLIT_BYTES;
    for (int k = 0; k < COUT; k++) {
        float v = W2[(size_t)k * MPTS + mt * 128 + ml] * 64.0f;
        __half a = __float2half_rn(v);
        __half b = __float2half_rn(v - __half2float(a));
        uint32_t off = (uint32_t)(k >> 6) * TILE_BYTES + SW128((uint32_t)(ml * 128 + (k & 63) * 2));
        *(__half*)(base + off) = a;
        *(__half*)(base + SPLIT_BYTES + off) = b;
    }
}

// ---------------- kernel A: f = relu(feats^T W1 + b1) -> fp16 2-split tiles ----
__global__ __launch_bounds__(256) void k_feat(const float* __restrict__ feats,
                                              const float* __restrict__ W1,
                                              const float* __restrict__ b1) {
    extern __shared__ float sm[];
    float* sX = sm;              // [64][132]
    float* sW = sm + 64 * 132;   // [64][128]
    const int b  = blockIdx.y;
    const int ntile = blockIdx.x;
    const int n0 = ntile * 128;
    const int t  = threadIdx.x;

#pragma unroll
    for (int i = 0; i < 8; i++) {
        int lin = t + 256 * i;
        int c = lin >> 5, q = lin & 31;
        float4 v = *(const float4*)(feats + ((size_t)(b * CIN + c)) * NPTS + n0 + 4 * q);
        *(float4*)(sX + c * 132 + 4 * q) = v;
    }
#pragma unroll
    for (int i = 0; i < 8; i++) {
        int lin = t + 256 * i;
        int c = lin >> 5, q = lin & 31;
        *(float4*)(sW + c * 128 + 4 * q) = *(const float4*)(W1 + c * 128 + 4 * q);
    }
    __syncthreads();

    const int db = (t & 15) * 8;
    const int nb = (t >> 4) * 8;

    float acc[8][8];
#pragma unroll
    for (int i = 0; i < 8; i++)
#pragma unroll
        for (int j = 0; j < 8; j++) acc[i][j] = 0.0f;

    for (int c = 0; c < CIN; c++) {
        float x[8], w[8];
#pragma unroll
        for (int i = 0; i < 8; i++) x[i] = sX[c * 132 + nb + i];
#pragma unroll
        for (int j = 0; j < 8; j++) w[j] = sW[c * 128 + db + j];
#pragma unroll
        for (int i = 0; i < 8; i++)
#pragma unroll
            for (int j = 0; j < 8; j++) acc[i][j] = fmaf(x[i], w[j], acc[i][j]);
    }

    float bias[8];
#pragma unroll
    for (int j = 0; j < 8; j++) bias[j] = b1[db + j];

    unsigned char* tb = g_fsplit + ((size_t)(b * NTILES + ntile) * 2) * SPLIT_BYTES
                      + (db >> 6) * TILE_BYTES;

#pragma unroll
    for (int i = 0; i < 8; i++) {
        float o[8];
#pragma unroll
        for (int j = 0; j < 8; j++) o[j] = fmaxf(acc[i][j] + bias[j], 0.0f);
        __half ha[8], hb[8];
#pragma unroll
        for (int j = 0; j < 8; j++) {
            ha[j] = __float2half_rn(o[j]);
            hb[j] = __float2half_rn(o[j] - __half2float(ha[j]));
        }
        uint4 pa, pb;
        pa.x = pk2h(ha[0], ha[1]); pa.y = pk2h(ha[2], ha[3]);
        pa.z = pk2h(ha[4], ha[5]); pa.w = pk2h(ha[6], ha[7]);
        pb.x = pk2h(hb[0], hb[1]); pb.y = pk2h(hb[2], hb[3]);
        pb.z = pk2h(hb[4], hb[5]); pb.w = pk2h(hb[6], hb[7]);
        uint32_t off = SW128((uint32_t)((nb + i) * 128 + (db & 63) * 2));
        *(uint4*)(tb + off) = pa;
        *(uint4*)(tb + SPLIT_BYTES + off) = pb;
    }
}

// ---------------- kernel B: persistent HMMA w-GEMM (fp16 2-split, 3 products) ----
// chunk-stage pipeline: one 64KB stage per chunk (f_a + f_b), double buffered.
// Epilogue in exp domain: argmax(w+g) == argmax(e^w / t), t = -ln(u+eps)+eps.
#define SM_W2   0                       // 2 x 32768 = 65536
#define SM_F    65536                   // 2 x 65536 = 131072
#define SM_BEST 196608                  // 128 x 8
#define SM_TOT  197632

__global__ __launch_bounds__(512, 1) void k_main(const float* __restrict__ u) {
    extern __shared__ unsigned char smc[];
    __shared__ int s_uid;
    const uint32_t smem_base = smem_u32(smc);
    const int t = threadIdx.x, lane = t & 31, wid = t >> 5;
    const int wm = wid >> 2, wn = wid & 3;
    unsigned long long* sBest = (unsigned long long*)(smc + SM_BEST);

    // A (W2, m-major): x4 -> a0..a3 of mma.row.col
    const uint32_t a_row = (uint32_t)((wm * 32 + (lane & 15)) * 128 + (lane >> 4) * 16);
    // B (f, n-major): x4 -> {n0-7/k0-7, n0-7/k8-15, n8-15/k0-7, n8-15/k8-15}
    const uint32_t b_row = (uint32_t)((wn * 32 + ((lane & 16) >> 1) + (lane & 7)) * 128
                                      + ((lane >> 3) & 1) * 16);

    while (true) {
        if (t == 0) s_uid = atomicAdd(&g_ctr, 1);
        __syncthreads();
        const int uid = s_uid;
        if (uid >= NUNITS) break;
        const int mt = uid & 31, b = (uid >> 5) & 1, np = uid >> 6;

        if (t < 128) sBest[t] = 0ULL;
        {   // W2 splits (64KB) -> smem
            const uint4* src = (const uint4*)(g_w2split + (size_t)mt * 2 * SPLIT_BYTES);
            uint4* dst = (uint4*)(smc + SM_W2);
#pragma unroll
            for (int i = 0; i < 8; i++) dst[t + 512 * i] = src[t + 512 * i];
        }
        __syncthreads();

        const unsigned char* fsrc = g_fsplit + ((size_t)(b * NTILES + np * NCHUNKS) * 2) * SPLIT_BYTES;
        {   // prologue: chunk 0 -> buf 0
            uint32_t d = smem_base + SM_F + t * 16;
            const unsigned char* sp = fsrc + t * 16;
#pragma unroll
            for (int i = 0; i < 8; i++) cp16(d + i * 8192, sp + i * 8192);
            CP_COMMIT();
        }

        float acc[2][4][4];
#pragma unroll
        for (int mi = 0; mi < 2; mi++)
#pragma unroll
            for (int ni = 0; ni < 4; ni++)
#pragma unroll
                for (int q = 0; q < 4; q++) acc[mi][ni][q] = 0.0f;
        float bv[4]; int bn[4];
#pragma unroll
        for (int q = 0; q < 4; q++) { bv[q] = 0.0f; bn[q] = 0; }

        const float* u_unit = u + (size_t)b * NPTS * MPTS
                            + ((size_t)np * NPART + wn * 32 + 2 * (lane & 3)) * MPTS
                            + (mt * 128 + wm * 32 + (lane >> 2));
        const int n_unit = np * NPART + wn * 32 + 2 * (lane & 3);

        for (int c = 0; c < NCHUNKS; c++) {
            const int buf = c & 1;
            CP_WAIT0();
            __syncthreads();
            if (c + 1 < NCHUNKS) {
                uint32_t d = smem_base + SM_F + (buf ^ 1) * CHUNK_BYTES + t * 16;
                const unsigned char* sp = fsrc + (size_t)(c + 1) * CHUNK_BYTES + t * 16;
#pragma unroll
                for (int i = 0; i < 8; i++) cp16(d + i * 8192, sp + i * 8192);
            }
            CP_COMMIT();

            const uint32_t fa0 = smem_base + SM_F + buf * CHUNK_BYTES;   // f_a tiles
            const uint32_t fb1 = fa0 + SPLIT_BYTES;                      // f_b tiles

            // ---- product block 1: f_a x {w_a, w_b} (128 mma) ----
#pragma unroll
            for (int kh = 0; kh < 2; kh++) {
                const uint32_t fhb = fa0 + kh * TILE_BYTES;
                const uint32_t whb = smem_base + SM_W2 + kh * TILE_BYTES;
#pragma unroll
                for (int ks = 0; ks < 4; ks++) {
                    uint32_t bf0[4], bf1[4];
                    ldsm_x4(bf0, fhb + SW128(b_row + ks * 32));
                    ldsm_x4(bf1, fhb + SW128(b_row + 2048 + ks * 32));
#pragma unroll
                    for (int sw = 0; sw < 2; sw++)
#pragma unroll
                        for (int mi = 0; mi < 2; mi++) {
                            uint32_t af[4];
                            ldsm_x4(af, whb + sw * SPLIT_BYTES + SW128(a_row + mi * 2048 + ks * 32));
                            mma16816(acc[mi][0], af, bf0);
                            mma16816(acc[mi][1], af, bf0 + 2);
                            mma16816(acc[mi][2], af, bf1);
                            mma16816(acc[mi][3], af, bf1 + 2);
                        }
                }
            }

            // ---- u prefetch (32 streaming LDG) — latency hides under block 2 ----
            const float* uc = u_unit + (size_t)(c * 128) * MPTS;
            float uu[32];
#pragma unroll
            for (int mi = 0; mi < 2; mi++)
#pragma unroll
                for (int hh = 0; hh < 2; hh++)
#pragma unroll
                    for (int ni = 0; ni < 4; ni++)
#pragma unroll
                        for (int j = 0; j < 2; j++)
                            uu[mi * 16 + hh * 8 + ni * 2 + j] =
                                __ldcs(uc + (size_t)(ni * 8 + j) * MPTS + mi * 16 + hh * 8);

            // ---- product block 2: f_b x w_a (64 mma) ----
#pragma unroll
            for (int kh = 0; kh < 2; kh++) {
                const uint32_t fhb = fb1 + kh * TILE_BYTES;
                const uint32_t whb = smem_base + SM_W2 + kh * TILE_BYTES;
#pragma unroll
                for (int ks = 0; ks < 4; ks++) {
                    uint32_t bf0[4], bf1[4];
                    ldsm_x4(bf0, fhb + SW128(b_row + ks * 32));
                    ldsm_x4(bf1, fhb + SW128(b_row + 2048 + ks * 32));
#pragma unroll
                    for (int mi = 0; mi < 2; mi++) {
                        uint32_t af[4];
                        ldsm_x4(af, whb + SW128(a_row + mi * 2048 + ks * 32));
                        mma16816(acc[mi][0], af, bf0);
                        mma16816(acc[mi][1], af, bf0 + 2);
                        mma16816(acc[mi][2], af, bf1);
                        mma16816(acc[mi][3], af, bf1 + 2);
                    }
                }
            }

            // ---- epilogue: exp-domain gumbel argmax (one log per element) ----
            const int n0 = n_unit + c * 128;
#pragma unroll
            for (int mi = 0; mi < 2; mi++)
#pragma unroll
                for (int hh = 0; hh < 2; hh++) {
                    const int slot = mi * 2 + hh;
                    float lbv = bv[slot]; int lbn = bn[slot];
#pragma unroll
                    for (int ni = 0; ni < 4; ni++)
#pragma unroll
                        for (int j = 0; j < 2; j++) {
                            float val = acc[mi][ni][hh * 2 + j];
                            float tt = fast_nlog(uu[mi * 16 + hh * 8 + ni * 2 + j] + EPSF) + EPSF;
                            float ew = __expf(val * 0.015625f);      // e^(w/64 scale)
                            if (ew > lbv * tt) {                     // e^w/t > bv
                                lbv = __fdividef(ew, tt);            // rare accept
                                lbn = n0 + ni * 8 + j;
                            }
                            acc[mi][ni][hh * 2 + j] = 0.0f;
                        }
                    bv[slot] = lbv; bn[slot] = lbn;
                }
        }

        // flush unit results (exp-domain scores are >0 and globally comparable)
#pragma unroll
        for (int mi = 0; mi < 2; mi++)
#pragma unroll
            for (int hh = 0; hh < 2; hh++) {
                const int slot = mi * 2 + hh;
                unsigned long long key = ((unsigned long long)enc_f(bv[slot]) << 32)
                                       | (0xFFFFFFFFu - (uint32_t)bn[slot]);
                atomicMax(&sBest[wm * 32 + mi * 16 + hh * 8 + (lane >> 2)], key);
            }
        __syncthreads();
        if (t < 128) atomicMax(&g_best[(size_t)b * MPTS + mt * 128 + t], sBest[t]);
        __syncthreads();
    }
}

// ---------------- kernel C: decode idx, write xyz + indices ----------------
__global__ void k_pick(const float* __restrict__ xyzs, float* __restrict__ out) {
    int i = blockIdx.x * blockDim.x + threadIdx.x;
    if (i >= NB * MPTS) return;
    int b = i / MPTS;
    unsigned long long key = g_best[i];
    int n = (int)(0xFFFFFFFFu - (unsigned int)(key & 0xFFFFFFFFull));
    g_idx[i] = n;
    const float* x = xyzs + ((size_t)b * NPTS + n) * 3;
    out[XYZ_OFF + 3 * i + 0] = x[0];
    out[XYZ_OFF + 3 * i + 1] = x[1];
    out[XYZ_OFF + 3 * i + 2] = x[2];
    out[IDX_OFF + i] = (float)n;
}

// ---------------- kernel D: gather features (b, Cout, M) from fp16 splits ----
__global__ void k_gather(float* __restrict__ out) {
    int j = blockIdx.x * blockDim.x + threadIdx.x;
    if (j >= NB * COUT * MPTS) return;
    int b = j / (COUT * MPTS);
    int d = (j / MPTS) % COUT;
    int m = j % MPTS;
    int n = g_idx[b * MPTS + m];
    const unsigned char* tb = g_fsplit + ((size_t)(b * NTILES + (n >> 7)) * 2) * SPLIT_BYTES
                            + (d >> 6) * TILE_BYTES;
    uint32_t off = SW128((uint32_t)((n & 127) * 128 + (d & 63) * 2));
    float fa = __half2float(*(const __half*)(tb + off));
    float fb = __half2float(*(const __half*)(tb + SPLIT_BYTES + off));
    out[FEAT_OFF + j] = fa + fb;
}

// ---------------- launch ----------------
extern "C" void kernel_launch(void* const* d_in, const int* in_sizes, int n_in,
                              void* d_out, int out_size) {
    const float* xyzs  = (const float*)d_in[0];
    const float* feats = (const float*)d_in[1];
    const float* u     = (const float*)d_in[2];
    const float* W1    = (const float*)d_in[3];
    const float* b1    = (const float*)d_in[4];
    const float* W2    = (const float*)d_in[5];
    // d_in[6] = b2: constant per m-column -> cannot change the argmax; unused.
    float* out = (float*)d_out;

    const int smemA = (64 * 132 + 64 * 128) * 4;
    cudaFuncSetAttribute(k_feat, cudaFuncAttributeMaxDynamicSharedMemorySize, smemA);
    cudaFuncSetAttribute(k_main, cudaFuncAttributeMaxDynamicSharedMemorySize, SM_TOT);

    k_w2split<<<MTILES, 128>>>(W2);
    k_feat<<<dim3(NTILES, NB), 256, smemA>>>(feats, W1, b1);
    k_main<<<NCTA, 512, SM_TOT>>>(u);
    k_pick<<<(NB * MPTS + 255) / 256, 256>>>(xyzs, out);
    k_gather<<<(NB * COUT * MPTS + 255) / 256, 256>>>(out);
}

// round 14
// speedup vs baseline: 1.8697x; 1.8697x over previous
#include <cuda_runtime.h>
#include <cuda_fp16.h>
#include <cstdint>
#include <math.h>

#define NB    2
#define NPTS  16384
#define MPTS  4096
#define CIN   64
#define COUT  128
#define EPSF  1e-10f

#define NSPLIT   16
#define NPART    (NPTS/NSPLIT)      // 1024
#define NCHUNKS  (NPART/128)        // 8
#define NTILES   (NPTS/128)         // 128 per batch
#define MTILES   (MPTS/128)         // 32
#define NUNITS   (MTILES*NSPLIT*NB) // 1024
#define NCTA     152

#define XYZ_OFF  0
#define FEAT_OFF (NB*MPTS*3)
#define IDX_OFF  (FEAT_OFF + NB*COUT*MPTS)

// tile block: [128 rows][64 fp16 cols] SW128 image = 16384 B
// per ntile: [f_a kh0, f_a kh1, f_b kh0, f_b kh1] = 65536 B contiguous
#define TILE_BYTES   16384
#define SPLIT_BYTES  32768
#define CHUNK_BYTES  65536

// ---------------- device scratch ----------------
__device__ __align__(1024) unsigned char g_fsplit[(size_t)NB*NTILES*2*SPLIT_BYTES];  // 16.8 MB
__device__ __align__(1024) unsigned char g_w2split[(size_t)MTILES*2*SPLIT_BYTES];    // 2 MB
__device__ unsigned long long  g_best[NB*MPTS];
__device__ int                 g_idx[NB*MPTS];
__device__ int                 g_ctr;

// ---------------- helpers ----------------
__device__ __forceinline__ uint32_t smem_u32(const void* p) {
    uint32_t a;
    asm("{ .reg .u64 t; cvta.to.shared.u64 t, %1; cvt.u32.u64 %0, t; }" : "=r"(a) : "l"(p));
    return a;
}
#define SW128(x) ((x) ^ (((x) >> 3) & 0x70))

__device__ __forceinline__ uint32_t enc_f(float x) {
    uint32_t u = __float_as_uint(x);
    return u ^ (((uint32_t)((int32_t)u >> 31)) | 0x80000000u);
}
__device__ __forceinline__ uint32_t pk2h(__half lo, __half hi) {
    __half2 t(lo, hi);
    return *(uint32_t*)&t;
}
// fast accurate -ln(x) for normal fp32 x: atanh-form poly, abs err ~1e-7,
// near-exact relative accuracy for x near 1 (where the argmax winners live).
// Used for the INNER log only — MUFU.LG2's absolute error would be ~300%
// relative on t1 ~ 1e-7 (the winner region).
__device__ __forceinline__ float fast_nlog(float x) {
    int i = __float_as_int(x);
    int tt = i - 0x3F3504F3;                   // bits of sqrt(0.5)
    int e  = tt >> 23;
    float m = __int_as_float(i - (e << 23));   // m in [0.7071, 1.4142)
    float s = __fdividef(m - 1.0f, m + 1.0f);  // |s| <= 0.1716
    float s2 = s * s;
    float p = fmaf(s2, 0.11111111f, 0.14285715f);
    p = fmaf(s2, p, 0.2f);
    p = fmaf(s2, p, 0.33333334f);
    p = fmaf(s2, p, 1.0f);
    float lm = (s + s) * p;                    // ln(m)
    float ef = (float)e;
    float res = fmaf(ef, -0.693359375f, -lm);  // -e*ln2_hi - ln(m)
    return fmaf(ef, 2.12194440e-4f, res);      // + e*ln2_lo_neg
}

__device__ __forceinline__ void ldsm_x4(uint32_t* r, uint32_t addr) {
    asm volatile("ldmatrix.sync.aligned.m8n8.x4.shared.b16 {%0,%1,%2,%3}, [%4];"
        : "=r"(r[0]), "=r"(r[1]), "=r"(r[2]), "=r"(r[3]) : "r"(addr));
}
__device__ __forceinline__ void mma16816(float* c, const uint32_t* a, const uint32_t* b) {
    asm volatile("mma.sync.aligned.m16n8k16.row.col.f32.f16.f16.f32 "
        "{%0,%1,%2,%3}, {%4,%5,%6,%7}, {%8,%9}, {%0,%1,%2,%3};"
        : "+f"(c[0]), "+f"(c[1]), "+f"(c[2]), "+f"(c[3])
        : "r"(a[0]), "r"(a[1]), "r"(a[2]), "r"(a[3]), "r"(b[0]), "r"(b[1]));
}
__device__ __forceinline__ void cp16(uint32_t dst, const void* src) {
    asm volatile("cp.async.cg.shared.global [%0], [%1], 16;" :: "r"(dst), "l"(src) : "memory");
}
#define CP_COMMIT() asm volatile("cp.async.commit_group;" ::: "memory")
#define CP_WAIT0()  asm volatile("cp.async.wait_group 0;" ::: "memory")

// ---------------- kernel W: split 64*W2^T into fp16 SW128 tiles + init ----------------
__global__ void k_w2split(const float* __restrict__ W2) {
    int mt = blockIdx.x, ml = threadIdx.x;
    if (mt == 0 && ml == 0) g_ctr = 0;
    for (int i = mt * 128 + ml; i < NB * MPTS; i += MTILES * 128) g_best[i] = 0ULL;
    unsigned char* base = g_w2split + (size_t)mt * 2 * SPLIT_BYTES;
    for (int k = 0; k < COUT; k++) {
        float v = W2[(size_t)k * MPTS + mt * 128 + ml] * 64.0f;
        __half a = __float2half_rn(v);
        __half b = __float2half_rn(v - __half2float(a));
        uint32_t off = (uint32_t)(k >> 6) * TILE_BYTES + SW128((uint32_t)(ml * 128 + (k & 63) * 2));
        *(__half*)(base + off) = a;
        *(__half*)(base + SPLIT_BYTES + off) = b;
    }
}

// ---------------- kernel A: f = relu(feats^T W1 + b1) -> fp16 2-split tiles ----
__global__ __launch_bounds__(256) void k_feat(const float* __restrict__ feats,
                                              const float* __restrict__ W1,
                                              const float* __restrict__ b1) {
    extern __shared__ float sm[];
    float* sX = sm;              // [64][132]
    float* sW = sm + 64 * 132;   // [64][128]
    const int b  = blockIdx.y;
    const int ntile = blockIdx.x;
    const int n0 = ntile * 128;
    const int t  = threadIdx.x;

#pragma unroll
    for (int i = 0; i < 8; i++) {
        int lin = t + 256 * i;
        int c = lin >> 5, q = lin & 31;
        float4 v = *(const float4*)(feats + ((size_t)(b * CIN + c)) * NPTS + n0 + 4 * q);
        *(float4*)(sX + c * 132 + 4 * q) = v;
    }
#pragma unroll
    for (int i = 0; i < 8; i++) {
        int lin = t + 256 * i;
        int c = lin >> 5, q = lin & 31;
        *(float4*)(sW + c * 128 + 4 * q) = *(const float4*)(W1 + c * 128 + 4 * q);
    }
    __syncthreads();

    const int db = (t & 15) * 8;
    const int nb = (t >> 4) * 8;

    float acc[8][8];
#pragma unroll
    for (int i = 0; i < 8; i++)
#pragma unroll
        for (int j = 0; j < 8; j++) acc[i][j] = 0.0f;

    for (int c = 0; c < CIN; c++) {
        float x[8], w[8];
#pragma unroll
        for (int i = 0; i < 8; i++) x[i] = sX[c * 132 + nb + i];
#pragma unroll
        for (int j = 0; j < 8; j++) w[j] = sW[c * 128 + db + j];
#pragma unroll
        for (int i = 0; i < 8; i++)
#pragma unroll
            for (int j = 0; j < 8; j++) acc[i][j] = fmaf(x[i], w[j], acc[i][j]);
    }

    float bias[8];
#pragma unroll
    for (int j = 0; j < 8; j++) bias[j] = b1[db + j];

    unsigned char* tb = g_fsplit + ((size_t)(b * NTILES + ntile) * 2) * SPLIT_BYTES
                      + (db >> 6) * TILE_BYTES;

#pragma unroll
    for (int i = 0; i < 8; i++) {
        float o[8];
#pragma unroll
        for (int j = 0; j < 8; j++) o[j] = fmaxf(acc[i][j] + bias[j], 0.0f);
        __half ha[8], hb[8];
#pragma unroll
        for (int j = 0; j < 8; j++) {
            ha[j] = __float2half_rn(o[j]);
            hb[j] = __float2half_rn(o[j] - __half2float(ha[j]));
        }
        uint4 pa, pb;
        pa.x = pk2h(ha[0], ha[1]); pa.y = pk2h(ha[2], ha[3]);
        pa.z = pk2h(ha[4], ha[5]); pa.w = pk2h(ha[6], ha[7]);
        pb.x = pk2h(hb[0], hb[1]); pb.y = pk2h(hb[2], hb[3]);
        pb.z = pk2h(hb[4], hb[5]); pb.w = pk2h(hb[6], hb[7]);
        uint32_t off = SW128((uint32_t)((nb + i) * 128 + (db & 63) * 2));
        *(uint4*)(tb + off) = pa;
        *(uint4*)(tb + SPLIT_BYTES + off) = pb;
    }
}

// ---------------- kernel B: persistent HMMA w-GEMM (fp16 2-split, 3 products) ----
// chunk-stage pipeline: one 64KB stage per chunk (f_a + f_b), double buffered.
#define SM_W2   0                       // 2 x 32768 = 65536
#define SM_F    65536                   // 2 x 65536 = 131072
#define SM_BEST 196608                  // 128 x 8
#define SM_TOT  197632

__global__ __launch_bounds__(512, 1) void k_main(const float* __restrict__ u) {
    extern __shared__ unsigned char smc[];
    __shared__ int s_uid;
    const uint32_t smem_base = smem_u32(smc);
    const int t = threadIdx.x, lane = t & 31, wid = t >> 5;
    const int wm = wid >> 2, wn = wid & 3;
    unsigned long long* sBest = (unsigned long long*)(smc + SM_BEST);

    // A (W2, m-major): x4 -> a0..a3 of mma.row.col
    const uint32_t a_row = (uint32_t)((wm * 32 + (lane & 15)) * 128 + (lane >> 4) * 16);
    // B (f, n-major): x4 -> {n0-7/k0-7, n0-7/k8-15, n8-15/k0-7, n8-15/k8-15}
    const uint32_t b_row = (uint32_t)((wn * 32 + ((lane & 16) >> 1) + (lane & 7)) * 128
                                      + ((lane >> 3) & 1) * 16);

    while (true) {
        if (t == 0) s_uid = atomicAdd(&g_ctr, 1);
        __syncthreads();
        const int uid = s_uid;
        if (uid >= NUNITS) break;
        const int mt = uid & 31, b = (uid >> 5) & 1, np = uid >> 6;

        if (t < 128) sBest[t] = 0ULL;
        {   // W2 splits (64KB) -> smem
            const uint4* src = (const uint4*)(g_w2split + (size_t)mt * 2 * SPLIT_BYTES);
            uint4* dst = (uint4*)(smc + SM_W2);
#pragma unroll
            for (int i = 0; i < 8; i++) dst[t + 512 * i] = src[t + 512 * i];
        }
        __syncthreads();

        const unsigned char* fsrc = g_fsplit + ((size_t)(b * NTILES + np * NCHUNKS) * 2) * SPLIT_BYTES;
        {   // prologue: chunk 0 -> buf 0
            uint32_t d = smem_base + SM_F + t * 16;
            const unsigned char* sp = fsrc + t * 16;
#pragma unroll
            for (int i = 0; i < 8; i++) cp16(d + i * 8192, sp + i * 8192);
            CP_COMMIT();
        }

        float acc[2][4][4];
#pragma unroll
        for (int mi = 0; mi < 2; mi++)
#pragma unroll
            for (int ni = 0; ni < 4; ni++)
#pragma unroll
                for (int q = 0; q < 4; q++) acc[mi][ni][q] = 0.0f;
        float bv[4]; int bn[4];
#pragma unroll
        for (int q = 0; q < 4; q++) { bv[q] = -1e38f; bn[q] = 0; }

        const float* u_unit = u + (size_t)b * NPTS * MPTS
                            + ((size_t)np * NPART + wn * 32 + 2 * (lane & 3)) * MPTS
                            + (mt * 128 + wm * 32 + (lane >> 2));
        const int n_unit = np * NPART + wn * 32 + 2 * (lane & 3);

        for (int c = 0; c < NCHUNKS; c++) {
            const int buf = c & 1;
            CP_WAIT0();
            __syncthreads();
            if (c + 1 < NCHUNKS) {
                uint32_t d = smem_base + SM_F + (buf ^ 1) * CHUNK_BYTES + t * 16;
                const unsigned char* sp = fsrc + (size_t)(c + 1) * CHUNK_BYTES + t * 16;
#pragma unroll
                for (int i = 0; i < 8; i++) cp16(d + i * 8192, sp + i * 8192);
            }
            CP_COMMIT();

            const uint32_t fa0 = smem_base + SM_F + buf * CHUNK_BYTES;   // f_a tiles
            const uint32_t fb1 = fa0 + SPLIT_BYTES;                      // f_b tiles

            // ---- product block 1: f_a x {w_a, w_b} (128 mma) ----
#pragma unroll
            for (int kh = 0; kh < 2; kh++) {
                const uint32_t fhb = fa0 + kh * TILE_BYTES;
                const uint32_t whb = smem_base + SM_W2 + kh * TILE_BYTES;
#pragma unroll
                for (int ks = 0; ks < 4; ks++) {
                    uint32_t bf0[4], bf1[4];
                    ldsm_x4(bf0, fhb + SW128(b_row + ks * 32));
                    ldsm_x4(bf1, fhb + SW128(b_row + 2048 + ks * 32));
#pragma unroll
                    for (int sw = 0; sw < 2; sw++)
#pragma unroll
                        for (int mi = 0; mi < 2; mi++) {
                            uint32_t af[4];
                            ldsm_x4(af, whb + sw * SPLIT_BYTES + SW128(a_row + mi * 2048 + ks * 32));
                            mma16816(acc[mi][0], af, bf0);
                            mma16816(acc[mi][1], af, bf0 + 2);
                            mma16816(acc[mi][2], af, bf1);
                            mma16816(acc[mi][3], af, bf1 + 2);
                        }
                }
            }

            // ---- u prefetch (32 LDG) — latency hides under product block 2 ----
            const float* uc = u_unit + (size_t)(c * 128) * MPTS;
            float uu[32];
#pragma unroll
            for (int mi = 0; mi < 2; mi++)
#pragma unroll
                for (int hh = 0; hh < 2; hh++)
#pragma unroll
                    for (int ni = 0; ni < 4; ni++)
#pragma unroll
                        for (int j = 0; j < 2; j++)
                            uu[mi * 16 + hh * 8 + ni * 2 + j] =
                                __ldg(uc + (size_t)(ni * 8 + j) * MPTS + mi * 16 + hh * 8);

            // ---- product block 2: f_b x w_a (64 mma) ----
#pragma unroll
            for (int kh = 0; kh < 2; kh++) {
                const uint32_t fhb = fb1 + kh * TILE_BYTES;
                const uint32_t whb = smem_base + SM_W2 + kh * TILE_BYTES;
#pragma unroll
                for (int ks = 0; ks < 4; ks++) {
                    uint32_t bf0[4], bf1[4];
                    ldsm_x4(bf0, fhb + SW128(b_row + ks * 32));
                    ldsm_x4(bf1, fhb + SW128(b_row + 2048 + ks * 32));
#pragma unroll
                    for (int mi = 0; mi < 2; mi++) {
                        uint32_t af[4];
                        ldsm_x4(af, whb + SW128(a_row + mi * 2048 + ks * 32));
                        mma16816(acc[mi][0], af, bf0);
                        mma16816(acc[mi][1], af, bf0 + 2);
                        mma16816(acc[mi][2], af, bf1);
                        mma16816(acc[mi][3], af, bf1 + 2);
                    }
                }
            }

            // ---- epilogue: gumbel + argmax (accurate inner log, fast outer) ----
            const int n0 = n_unit + c * 128;
#pragma unroll
            for (int mi = 0; mi < 2; mi++)
#pragma unroll
                for (int hh = 0; hh < 2; hh++) {
                    const int slot = mi * 2 + hh;
                    float lbv = bv[slot]; int lbn = bn[slot];
#pragma unroll
                    for (int ni = 0; ni < 4; ni++)
#pragma unroll
                        for (int j = 0; j < 2; j++) {
                            float val = acc[mi][ni][hh * 2 + j];
                            float t1 = fast_nlog(uu[mi * 16 + hh * 8 + ni * 2 + j] + EPSF);
                            float g  = -__logf(t1 + EPSF);        // outer: |err| < ~6e-6 abs
                            float sc = fmaf(val, 0.015625f, g);   // /64 W2 scale
                            if (sc > lbv) { lbv = sc; lbn = n0 + ni * 8 + j; }
                            acc[mi][ni][hh * 2 + j] = 0.0f;
                        }
                    bv[slot] = lbv; bn[slot] = lbn;
                }
        }

        // flush unit results
#pragma unroll
        for (int mi = 0; mi < 2; mi++)
#pragma unroll
            for (int hh = 0; hh < 2; hh++) {
                const int slot = mi * 2 + hh;
                unsigned long long key = ((unsigned long long)enc_f(bv[slot]) << 32)
                                       | (0xFFFFFFFFu - (uint32_t)bn[slot]);
                atomicMax(&sBest[wm * 32 + mi * 16 + hh * 8 + (lane >> 2)], key);
            }
        __syncthreads();
        if (t < 128) atomicMax(&g_best[(size_t)b * MPTS + mt * 128 + t], sBest[t]);
        __syncthreads();
    }
}

// ---------------- kernel C: decode idx, write xyz + indices ----------------
__global__ void k_pick(const float* __restrict__ xyzs, float* __restrict__ out) {
    int i = blockIdx.x * blockDim.x + threadIdx.x;
    if (i >= NB * MPTS) return;
    int b = i / MPTS;
    unsigned long long key = g_best[i];
    int n = (int)(0xFFFFFFFFu - (unsigned int)(key & 0xFFFFFFFFull));
    g_idx[i] = n;
    const float* x = xyzs + ((size_t)b * NPTS + n) * 3;
    out[XYZ_OFF + 3 * i + 0] = x[0];
    out[XYZ_OFF + 3 * i + 1] = x[1];
    out[XYZ_OFF + 3 * i + 2] = x[2];
    out[IDX_OFF + i] = (float)n;
}

// ---------------- kernel D: gather features (b, Cout, M) from fp16 splits ----
__global__ void k_gather(float* __restrict__ out) {
    int j = blockIdx.x * blockDim.x + threadIdx.x;
    if (j >= NB * COUT * MPTS) return;
    int b = j / (COUT * MPTS);
    int d = (j / MPTS) % COUT;
    int m = j % MPTS;
    int n = g_idx[b * MPTS + m];
    const unsigned char* tb = g_fsplit + ((size_t)(b * NTILES + (n >> 7)) * 2) * SPLIT_BYTES
                            + (d >> 6) * TILE_BYTES;
    uint32_t off = SW128((uint32_t)((n & 127) * 128 + (d & 63) * 2));
    float fa = __half2float(*(const __half*)(tb + off));
    float fb = __half2float(*(const __half*)(tb + SPLIT_BYTES + off));
    out[FEAT_OFF + j] = fa + fb;
}

// ---------------- launch ----------------
extern "C" void kernel_launch(void* const* d_in, const int* in_sizes, int n_in,
                              void* d_out, int out_size) {
    const float* xyzs  = (const float*)d_in[0];
    const float* feats = (const float*)d_in[1];
    const float* u     = (const float*)d_in[2];
    const float* W1    = (const float*)d_in[3];
    const float* b1    = (const float*)d_in[4];
    const float* W2    = (const float*)d_in[5];
    // d_in[6] = b2: constant per m-column -> cannot change the argmax; unused.
    float* out = (float*)d_out;

    const int smemA = (64 * 132 + 64 * 128) * 4;
    cudaFuncSetAttribute(k_feat, cudaFuncAttributeMaxDynamicSharedMemorySize, smemA);
    cudaFuncSetAttribute(k_main, cudaFuncAttributeMaxDynamicSharedMemorySize, SM_TOT);

    k_w2split<<<MTILES, 128>>>(W2);
    k_feat<<<dim3(NTILES, NB), 256, smemA>>>(feats, W1, b1);
    k_main<<<NCTA, 512, SM_TOT>>>(u);
    k_pick<<<(NB * MPTS + 255) / 256, 256>>>(xyzs, out);
    k_gather<<<(NB * COUT * MPTS + 255) / 256, 256>>>(out);
}

// round 15
// speedup vs baseline: 1.9728x; 1.0552x over previous
#include <cuda_runtime.h>
#include <cuda_fp16.h>
#include <cstdint>
#include <math.h>

#define NB    2
#define NPTS  16384
#define MPTS  4096
#define CIN   64
#define COUT  128
#define EPSF  1e-10f

#define NSPLIT   16
#define NPART    (NPTS/NSPLIT)      // 1024
#define NCHUNKS  (NPART/128)        // 8
#define NTILES   (NPTS/128)         // 128 per batch
#define MTILES   (MPTS/128)         // 32
#define NUNITS   (MTILES*NSPLIT*NB) // 1024
#define NCTA     152

#define XYZ_OFF  0
#define FEAT_OFF (NB*MPTS*3)
#define IDX_OFF  (FEAT_OFF + NB*COUT*MPTS)

// tile block: [128 rows][64 fp16 cols] SW128 image = 16384 B
// per ntile: [f_a kh0, f_a kh1, f_b kh0, f_b kh1] = 65536 B contiguous
#define TILE_BYTES   16384
#define SPLIT_BYTES  32768
#define CHUNK_BYTES  65536

// ---------------- device scratch ----------------
__device__ __align__(1024) unsigned char g_fsplit[(size_t)NB*NTILES*2*SPLIT_BYTES];  // 16.8 MB
__device__ __align__(1024) unsigned char g_w2split[(size_t)MTILES*2*SPLIT_BYTES];    // 2 MB
__device__ unsigned long long  g_best[NB*MPTS];
__device__ int                 g_idx[NB*MPTS];
__device__ int                 g_ctr;

// ---------------- helpers ----------------
__device__ __forceinline__ uint32_t smem_u32(const void* p) {
    uint32_t a;
    asm("{ .reg .u64 t; cvta.to.shared.u64 t, %1; cvt.u32.u64 %0, t; }" : "=r"(a) : "l"(p));
    return a;
}
#define SW128(x) ((x) ^ (((x) >> 3) & 0x70))

__device__ __forceinline__ uint32_t enc_f(float x) {
    uint32_t u = __float_as_uint(x);
    return u ^ (((uint32_t)((int32_t)u >> 31)) | 0x80000000u);
}
__device__ __forceinline__ uint32_t pk2h(__half lo, __half hi) {
    __half2 t(lo, hi);
    return *(uint32_t*)&t;
}
// fast accurate -ln(x): atanh-form poly, abs err ~1e-7, full relative accuracy
// near x=1 (winner region). INNER log only — MUFU.LG2's absolute error would
// be ~300% relative on t1 ~ 1e-7.
__device__ __forceinline__ float fast_nlog(float x) {
    int i = __float_as_int(x);
    int tt = i - 0x3F3504F3;                   // bits of sqrt(0.5)
    int e  = tt >> 23;
    float m = __int_as_float(i - (e << 23));   // m in [0.7071, 1.4142)
    float s = __fdividef(m - 1.0f, m + 1.0f);  // |s| <= 0.1716
    float s2 = s * s;
    float p = fmaf(s2, 0.11111111f, 0.14285715f);
    p = fmaf(s2, p, 0.2f);
    p = fmaf(s2, p, 0.33333334f);
    p = fmaf(s2, p, 1.0f);
    float lm = (s + s) * p;                    // ln(m)
    float ef = (float)e;
    float res = fmaf(ef, -0.693359375f, -lm);  // -e*ln2_hi - ln(m)
    return fmaf(ef, 2.12194440e-4f, res);      // + e*ln2_lo_neg
}

__device__ __forceinline__ void ldsm_x4(uint32_t* r, uint32_t addr) {
    asm volatile("ldmatrix.sync.aligned.m8n8.x4.shared.b16 {%0,%1,%2,%3}, [%4];"
        : "=r"(r[0]), "=r"(r[1]), "=r"(r[2]), "=r"(r[3]) : "r"(addr));
}
__device__ __forceinline__ void mma16816(float* c, const uint32_t* a, const uint32_t* b) {
    asm volatile("mma.sync.aligned.m16n8k16.row.col.f32.f16.f16.f32 "
        "{%0,%1,%2,%3}, {%4,%5,%6,%7}, {%8,%9}, {%0,%1,%2,%3};"
        : "+f"(c[0]), "+f"(c[1]), "+f"(c[2]), "+f"(c[3])
        : "r"(a[0]), "r"(a[1]), "r"(a[2]), "r"(a[3]), "r"(b[0]), "r"(b[1]));
}
__device__ __forceinline__ void cp16(uint32_t dst, const void* src) {
    asm volatile("cp.async.cg.shared.global [%0], [%1], 16;" :: "r"(dst), "l"(src) : "memory");
}
#define CP_COMMIT() asm volatile("cp.async.commit_group;" ::: "memory")
#define CP_WAIT0()  asm volatile("cp.async.wait_group 0;" ::: "memory")

// ---------------- kernel 0: init (also restores k_main at ncu launch #4) ----
__global__ void k_init() {
    int i = blockIdx.x * blockDim.x + threadIdx.x;
    if (i == 0) g_ctr = 0;
    if (i < NB * MPTS) g_best[i] = 0ULL;
}

// ---------------- kernel W: split 64*W2^T into fp16 SW128 tiles ----------------
__global__ void k_w2split(const float* __restrict__ W2) {
    int mt = blockIdx.x, ml = threadIdx.x;
    unsigned char* base = g_w2split + (size_t)mt * 2 * SPLIT_BYTES;
    for (int k = 0; k < COUT; k++) {
        float v = W2[(size_t)k * MPTS + mt * 128 + ml] * 64.0f;
        __half a = __float2half_rn(v);
        __half b = __float2half_rn(v - __half2float(a));
        uint32_t off = (uint32_t)(k >> 6) * TILE_BYTES + SW128((uint32_t)(ml * 128 + (k & 63) * 2));
        *(__half*)(base + off) = a;
        *(__half*)(base + SPLIT_BYTES + off) = b;
    }
}

// ---------------- kernel A: f = relu(feats^T W1 + b1) -> fp16 2-split tiles ----
__global__ __launch_bounds__(256) void k_feat(const float* __restrict__ feats,
                                              const float* __restrict__ W1,
                                              const float* __restrict__ b1) {
    extern __shared__ float sm[];
    float* sX = sm;              // [64][132]
    float* sW = sm + 64 * 132;   // [64][128]
    const int b  = blockIdx.y;
    const int ntile = blockIdx.x;
    const int n0 = ntile * 128;
    const int t  = threadIdx.x;

#pragma unroll
    for (int i = 0; i < 8; i++) {
        int lin = t + 256 * i;
        int c = lin >> 5, q = lin & 31;
        float4 v = *(const float4*)(feats + ((size_t)(b * CIN + c)) * NPTS + n0 + 4 * q);
        *(float4*)(sX + c * 132 + 4 * q) = v;
    }
#pragma unroll
    for (int i = 0; i < 8; i++) {
        int lin = t + 256 * i;
        int c = lin >> 5, q = lin & 31;
        *(float4*)(sW + c * 128 + 4 * q) = *(const float4*)(W1 + c * 128 + 4 * q);
    }
    __syncthreads();

    const int db = (t & 15) * 8;
    const int nb = (t >> 4) * 8;

    float acc[8][8];
#pragma unroll
    for (int i = 0; i < 8; i++)
#pragma unroll
        for (int j = 0; j < 8; j++) acc[i][j] = 0.0f;

    for (int c = 0; c < CIN; c++) {
        float x[8], w[8];
#pragma unroll
        for (int i = 0; i < 8; i++) x[i] = sX[c * 132 + nb + i];
#pragma unroll
        for (int j = 0; j < 8; j++) w[j] = sW[c * 128 + db + j];
#pragma unroll
        for (int i = 0; i < 8; i++)
#pragma unroll
            for (int j = 0; j < 8; j++) acc[i][j] = fmaf(x[i], w[j], acc[i][j]);
    }

    float bias[8];
#pragma unroll
    for (int j = 0; j < 8; j++) bias[j] = b1[db + j];

    unsigned char* tb = g_fsplit + ((size_t)(b * NTILES + ntile) * 2) * SPLIT_BYTES
                      + (db >> 6) * TILE_BYTES;

#pragma unroll
    for (int i = 0; i < 8; i++) {
        float o[8];
#pragma unroll
        for (int j = 0; j < 8; j++) o[j] = fmaxf(acc[i][j] + bias[j], 0.0f);
        __half ha[8], hb[8];
#pragma unroll
        for (int j = 0; j < 8; j++) {
            ha[j] = __float2half_rn(o[j]);
            hb[j] = __float2half_rn(o[j] - __half2float(ha[j]));
        }
        uint4 pa, pb;
        pa.x = pk2h(ha[0], ha[1]); pa.y = pk2h(ha[2], ha[3]);
        pa.z = pk2h(ha[4], ha[5]); pa.w = pk2h(ha[6], ha[7]);
        pb.x = pk2h(hb[0], hb[1]); pb.y = pk2h(hb[2], hb[3]);
        pb.z = pk2h(hb[4], hb[5]); pb.w = pk2h(hb[6], hb[7]);
        uint32_t off = SW128((uint32_t)((nb + i) * 128 + (db & 63) * 2));
        *(uint4*)(tb + off) = pa;
        *(uint4*)(tb + SPLIT_BYTES + off) = pb;
    }
}

// ---------------- kernel B: persistent HMMA w-GEMM (fp16 2-split, 3 products) ----
// Chunk-deferred epilogue: chunk c's gumbel/argmax runs inside chunk c+1's
// tensor-paced mma stream (operands in sacc, long completed) — no tensor-idle
// epilogue phase. u loads in 16-element half-batches to bound registers.
#define SM_W2   0                       // 2 x 32768 = 65536
#define SM_F    65536                   // 2 x 65536 = 131072
#define SM_BEST 196608                  // 128 x 8
#define SM_TOT  197632

__global__ __launch_bounds__(512, 1) void k_main(const float* __restrict__ u) {
    extern __shared__ unsigned char smc[];
    __shared__ int s_uid;
    const uint32_t smem_base = smem_u32(smc);
    const int t = threadIdx.x, lane = t & 31, wid = t >> 5;
    const int wm = wid >> 2, wn = wid & 3;
    unsigned long long* sBest = (unsigned long long*)(smc + SM_BEST);

    // A (W2, m-major): x4 -> a0..a3 of mma.row.col
    const uint32_t a_row = (uint32_t)((wm * 32 + (lane & 15)) * 128 + (lane >> 4) * 16);
    // B (f, n-major): x4 -> {n0-7/k0-7, n0-7/k8-15, n8-15/k0-7, n8-15/k8-15}
    const uint32_t b_row = (uint32_t)((wn * 32 + ((lane & 16) >> 1) + (lane & 7)) * 128
                                      + ((lane >> 3) & 1) * 16);

    while (true) {
        if (t == 0) s_uid = atomicAdd(&g_ctr, 1);
        __syncthreads();
        const int uid = s_uid;
        if (uid >= NUNITS) break;
        const int mt = uid & 31, b = (uid >> 5) & 1, np = uid >> 6;

        if (t < 128) sBest[t] = 0ULL;
        {   // W2 splits (64KB) -> smem
            const uint4* src = (const uint4*)(g_w2split + (size_t)mt * 2 * SPLIT_BYTES);
            uint4* dst = (uint4*)(smc + SM_W2);
#pragma unroll
            for (int i = 0; i < 8; i++) dst[t + 512 * i] = src[t + 512 * i];
        }
        __syncthreads();

        const unsigned char* fsrc = g_fsplit + ((size_t)(b * NTILES + np * NCHUNKS) * 2) * SPLIT_BYTES;
        {   // prologue: chunk 0 -> buf 0
            uint32_t d = smem_base + SM_F + t * 16;
            const unsigned char* sp = fsrc + t * 16;
#pragma unroll
            for (int i = 0; i < 8; i++) cp16(d + i * 8192, sp + i * 8192);
            CP_COMMIT();
        }

        float acc[2][4][4], sacc[2][4][4];
#pragma unroll
        for (int mi = 0; mi < 2; mi++)
#pragma unroll
            for (int ni = 0; ni < 4; ni++)
#pragma unroll
                for (int q = 0; q < 4; q++) acc[mi][ni][q] = 0.0f;
        float bv[4]; int bn[4];
#pragma unroll
        for (int q = 0; q < 4; q++) { bv[q] = -1e38f; bn[q] = 0; }

        const float* u_unit = u + (size_t)b * NPTS * MPTS
                            + ((size_t)np * NPART + wn * 32 + 2 * (lane & 3)) * MPTS
                            + (mt * 128 + wm * 32 + (lane >> 2));
        const int n_unit = np * NPART + wn * 32 + 2 * (lane & 3);
        float uu[16];

        for (int c = 0; c < NCHUNKS; c++) {
            const int buf = c & 1;
            const int cp = c - 1;                   // deferred-epilogue chunk
            CP_WAIT0();
            __syncthreads();
            if (c + 1 < NCHUNKS) {
                uint32_t d = smem_base + SM_F + (buf ^ 1) * CHUNK_BYTES + t * 16;
                const unsigned char* sp = fsrc + (size_t)(c + 1) * CHUNK_BYTES + t * 16;
#pragma unroll
                for (int i = 0; i < 8; i++) cp16(d + i * 8192, sp + i * 8192);
            }
            CP_COMMIT();

            // u half A (prev chunk, mi=0) — latency hides under block-1 backlog
            if (c > 0) {
                const float* uc = u_unit + (size_t)(cp * 128) * MPTS;
#pragma unroll
                for (int hh = 0; hh < 2; hh++)
#pragma unroll
                    for (int ni = 0; ni < 4; ni++)
#pragma unroll
                        for (int j = 0; j < 2; j++)
                            uu[hh * 8 + ni * 2 + j] = __ldg(uc + (size_t)(ni * 8 + j) * MPTS + hh * 8);
            }

            const uint32_t fa0 = smem_base + SM_F + buf * CHUNK_BYTES;   // f_a tiles
            const uint32_t fb1 = fa0 + SPLIT_BYTES;                      // f_b tiles

            // ---- product block 1: f_a x {w_a, w_b} (128 mma) ----
#pragma unroll
            for (int kh = 0; kh < 2; kh++) {
                const uint32_t fhb = fa0 + kh * TILE_BYTES;
                const uint32_t whb = smem_base + SM_W2 + kh * TILE_BYTES;
#pragma unroll
                for (int ks = 0; ks < 4; ks++) {
                    uint32_t bf0[4], bf1[4];
                    ldsm_x4(bf0, fhb + SW128(b_row + ks * 32));
                    ldsm_x4(bf1, fhb + SW128(b_row + 2048 + ks * 32));
#pragma unroll
                    for (int sw = 0; sw < 2; sw++)
#pragma unroll
                        for (int mi = 0; mi < 2; mi++) {
                            uint32_t af[4];
                            ldsm_x4(af, whb + sw * SPLIT_BYTES + SW128(a_row + mi * 2048 + ks * 32));
                            mma16816(acc[mi][0], af, bf0);
                            mma16816(acc[mi][1], af, bf0 + 2);
                            mma16816(acc[mi][2], af, bf1);
                            mma16816(acc[mi][3], af, bf1 + 2);
                        }
                }
            }

            // ---- deferred epilogue half A (prev chunk, mi=0) + u half B issue ----
            if (c > 0) {
                const int n0p = n_unit + cp * 128;
#pragma unroll
                for (int hh = 0; hh < 2; hh++) {
                    float lbv = bv[hh]; int lbn = bn[hh];
#pragma unroll
                    for (int ni = 0; ni < 4; ni++)
#pragma unroll
                        for (int j = 0; j < 2; j++) {
                            float t1 = fast_nlog(uu[hh * 8 + ni * 2 + j] + EPSF);
                            float g  = -__logf(t1 + EPSF);
                            float sc = fmaf(sacc[0][ni][hh * 2 + j], 0.015625f, g);
                            if (sc > lbv) { lbv = sc; lbn = n0p + ni * 8 + j; }
                        }
                    bv[hh] = lbv; bn[hh] = lbn;
                }
                const float* uc = u_unit + (size_t)(cp * 128) * MPTS;
#pragma unroll
                for (int hh = 0; hh < 2; hh++)
#pragma unroll
                    for (int ni = 0; ni < 4; ni++)
#pragma unroll
                        for (int j = 0; j < 2; j++)
                            uu[hh * 8 + ni * 2 + j] = __ldg(uc + (size_t)(ni * 8 + j) * MPTS + 16 + hh * 8);
            }

            // ---- product block 2: f_b x w_a (64 mma) ----
#pragma unroll
            for (int kh = 0; kh < 2; kh++) {
                const uint32_t fhb = fb1 + kh * TILE_BYTES;
                const uint32_t whb = smem_base + SM_W2 + kh * TILE_BYTES;
#pragma unroll
                for (int ks = 0; ks < 4; ks++) {
                    uint32_t bf0[4], bf1[4];
                    ldsm_x4(bf0, fhb + SW128(b_row + ks * 32));
                    ldsm_x4(bf1, fhb + SW128(b_row + 2048 + ks * 32));
#pragma unroll
                    for (int mi = 0; mi < 2; mi++) {
                        uint32_t af[4];
                        ldsm_x4(af, whb + SW128(a_row + mi * 2048 + ks * 32));
                        mma16816(acc[mi][0], af, bf0);
                        mma16816(acc[mi][1], af, bf0 + 2);
                        mma16816(acc[mi][2], af, bf1);
                        mma16816(acc[mi][3], af, bf1 + 2);
                    }
                }
            }

            // ---- deferred epilogue half B (prev chunk, mi=1) — hides in block-2 drain ----
            if (c > 0) {
                const int n0p = n_unit + cp * 128;
#pragma unroll
                for (int hh = 0; hh < 2; hh++) {
                    const int slot = 2 + hh;
                    float lbv = bv[slot]; int lbn = bn[slot];
#pragma unroll
                    for (int ni = 0; ni < 4; ni++)
#pragma unroll
                        for (int j = 0; j < 2; j++) {
                            float t1 = fast_nlog(uu[hh * 8 + ni * 2 + j] + EPSF);
                            float g  = -__logf(t1 + EPSF);
                            float sc = fmaf(sacc[1][ni][hh * 2 + j], 0.015625f, g);
                            if (sc > lbv) { lbv = sc; lbn = n0p + ni * 8 + j; }
                        }
                    bv[slot] = lbv; bn[slot] = lbn;
                }
            }

            // ---- hand off acc -> sacc, clear acc ----
#pragma unroll
            for (int mi = 0; mi < 2; mi++)
#pragma unroll
                for (int ni = 0; ni < 4; ni++)
#pragma unroll
                    for (int q = 0; q < 4; q++) {
                        sacc[mi][ni][q] = acc[mi][ni][q];
                        acc[mi][ni][q] = 0.0f;
                    }
        }

        // ---- tail: epilogue for the last chunk (from sacc) ----
        {
            const int cp = NCHUNKS - 1;
            const int n0p = n_unit + cp * 128;
            const float* uc = u_unit + (size_t)(cp * 128) * MPTS;
#pragma unroll
            for (int mi = 0; mi < 2; mi++) {
#pragma unroll
                for (int hh = 0; hh < 2; hh++)
#pragma unroll
                    for (int ni = 0; ni < 4; ni++)
#pragma unroll
                        for (int j = 0; j < 2; j++)
                            uu[hh * 8 + ni * 2 + j] =
                                __ldg(uc + (size_t)(ni * 8 + j) * MPTS + mi * 16 + hh * 8);
#pragma unroll
                for (int hh = 0; hh < 2; hh++) {
                    const int slot = mi * 2 + hh;
                    float lbv = bv[slot]; int lbn = bn[slot];
#pragma unroll
                    for (int ni = 0; ni < 4; ni++)
#pragma unroll
                        for (int j = 0; j < 2; j++) {
                            float t1 = fast_nlog(uu[hh * 8 + ni * 2 + j] + EPSF);
                            float g  = -__logf(t1 + EPSF);
                            float sc = fmaf(sacc[mi][ni][hh * 2 + j], 0.015625f, g);
                            if (sc > lbv) { lbv = sc; lbn = n0p + ni * 8 + j; }
                        }
                    bv[slot] = lbv; bn[slot] = lbn;
                }
            }
        }

        // flush unit results
#pragma unroll
        for (int mi = 0; mi < 2; mi++)
#pragma unroll
            for (int hh = 0; hh < 2; hh++) {
                const int slot = mi * 2 + hh;
                unsigned long long key = ((unsigned long long)enc_f(bv[slot]) << 32)
                                       | (0xFFFFFFFFu - (uint32_t)bn[slot]);
                atomicMax(&sBest[wm * 32 + mi * 16 + hh * 8 + (lane >> 2)], key);
            }
        __syncthreads();
        if (t < 128) atomicMax(&g_best[(size_t)b * MPTS + mt * 128 + t], sBest[t]);
        __syncthreads();
    }
}

// ---------------- kernel C: decode idx, write xyz + indices ----------------
__global__ void k_pick(const float* __restrict__ xyzs, float* __restrict__ out) {
    int i = blockIdx.x * blockDim.x + threadIdx.x;
    if (i >= NB * MPTS) return;
    int b = i / MPTS;
    unsigned long long key = g_best[i];
    int n = (int)(0xFFFFFFFFu - (unsigned int)(key & 0xFFFFFFFFull));
    g_idx[i] = n;
    const float* x = xyzs + ((size_t)b * NPTS + n) * 3;
    out[XYZ_OFF + 3 * i + 0] = x[0];
    out[XYZ_OFF + 3 * i + 1] = x[1];
    out[XYZ_OFF + 3 * i + 2] = x[2];
    out[IDX_OFF + i] = (float)n;
}

// ---------------- kernel D: gather features (b, Cout, M) from fp16 splits ----
__global__ void k_gather(float* __restrict__ out) {
    int j = blockIdx.x * blockDim.x + threadIdx.x;
    if (j >= NB * COUT * MPTS) return;
    int b = j / (COUT * MPTS);
    int d = (j / MPTS) % COUT;
    int m = j % MPTS;
    int n = g_idx[b * MPTS + m];
    const unsigned char* tb = g_fsplit + ((size_t)(b * NTILES + (n >> 7)) * 2) * SPLIT_BYTES
                            + (d >> 6) * TILE_BYTES;
    uint32_t off = SW128((uint32_t)((n & 127) * 128 + (d & 63) * 2));
    float fa = __half2float(*(const __half*)(tb + off));
    float fb = __half2float(*(const __half*)(tb + SPLIT_BYTES + off));
    out[FEAT_OFF + j] = fa + fb;
}

// ---------------- launch ----------------
extern "C" void kernel_launch(void* const* d_in, const int* in_sizes, int n_in,
                              void* d_out, int out_size) {
    const float* xyzs  = (const float*)d_in[0];
    const float* feats = (const float*)d_in[1];
    const float* u     = (const float*)d_in[2];
    const float* W1    = (const float*)d_in[3];
    const float* b1    = (const float*)d_in[4];
    const float* W2    = (const float*)d_in[5];
    // d_in[6] = b2: constant per m-column -> cannot change the argmax; unused.
    float* out = (float*)d_out;

    const int smemA = (64 * 132 + 64 * 128) * 4;
    cudaFuncSetAttribute(k_feat, cudaFuncAttributeMaxDynamicSharedMemorySize, smemA);
    cudaFuncSetAttribute(k_main, cudaFuncAttributeMaxDynamicSharedMemorySize, SM_TOT);

    k_init<<<(NB * MPTS + 255) / 256, 256>>>();
    k_w2split<<<MTILES, 128>>>(W2);
    k_feat<<<dim3(NTILES, NB), 256, smemA>>>(feats, W1, b1);
    k_main<<<NCTA, 512, SM_TOT>>>(u);
    k_pick<<<(NB * MPTS + 255) / 256, 256>>>(xyzs, out);
    k_gather<<<(NB * COUT * MPTS + 255) / 256, 256>>>(out);
}